// round 13
// baseline (speedup 1.0000x reference)
#include <cuda_runtime.h>

#define HWSZ 1444          // 38*38
#define WDIM 38
#define NA   25
#define NB   512
#define NPLANES (NB * NA)  // 12800

// Anchors: base * scale, scales {0.5, 0.75, 1.0, 1.25, 1.5}, matching
// np.concatenate([_BASE * s for s in scales]) in float32.
__constant__ float c_anchors[NA][2] = {
    {1.3221f*0.50f, 1.73145f*0.50f}, {3.19275f*0.50f, 4.00944f*0.50f},
    {5.05587f*0.50f, 8.09892f*0.50f}, {9.47112f*0.50f, 4.84053f*0.50f},
    {11.2364f*0.50f, 10.0071f*0.50f},
    {1.3221f*0.75f, 1.73145f*0.75f}, {3.19275f*0.75f, 4.00944f*0.75f},
    {5.05587f*0.75f, 8.09892f*0.75f}, {9.47112f*0.75f, 4.84053f*0.75f},
    {11.2364f*0.75f, 10.0071f*0.75f},
    {1.3221f*1.00f, 1.73145f*1.00f}, {3.19275f*1.00f, 4.00944f*1.00f},
    {5.05587f*1.00f, 8.09892f*1.00f}, {9.47112f*1.00f, 4.84053f*1.00f},
    {11.2364f*1.00f, 10.0071f*1.00f},
    {1.3221f*1.25f, 1.73145f*1.25f}, {3.19275f*1.25f, 4.00944f*1.25f},
    {5.05587f*1.25f, 8.09892f*1.25f}, {9.47112f*1.25f, 4.84053f*1.25f},
    {11.2364f*1.25f, 10.0071f*1.25f},
    {1.3221f*1.50f, 1.73145f*1.50f}, {3.19275f*1.50f, 4.00944f*1.50f},
    {5.05587f*1.50f, 8.09892f*1.50f}, {9.47112f*1.50f, 4.84053f*1.50f},
    {11.2364f*1.50f, 10.0071f*1.50f}
};

__device__ float        g_partials[NPLANES];
__device__ float        g_corr[NB];
__device__ unsigned int g_count = 0;

struct GT { float gxm, gxM, gym, gyM, gw, gh, gwh; };

__device__ __forceinline__ GT make_gt(float4 t4) {
    GT g;
    float gx = t4.x * 38.0f, gy = t4.y * 38.0f;
    g.gw = t4.z * 38.0f;  g.gh = t4.w * 38.0f;
    g.gxm = gx - g.gw * 0.5f;  g.gxM = gx + g.gw * 0.5f;
    g.gym = gy - g.gh * 0.5f;  g.gyM = gy + g.gh * 0.5f;
    g.gwh = g.gw * g.gh;
    return g;
}

__device__ __forceinline__ float sigmoid_fast(float x) {
    return __fdividef(1.0f, 1.0f + __expf(-x));
}

// Generic (non-special) cell loss contribution. Used identically in the main
// pass and in the correction so the special-cell generic term cancels exactly.
__device__ __forceinline__ float cell_generic(
    float px, float py, float pw, float ph, float pcin,
    float wf, float hf, float aw, float ah, const GT& g)
{
    float sx = sigmoid_fast(px);
    float sy = sigmoid_fast(py);
    float pc = sigmoid_fast(pcin);
    float bw = __expf(pw) * aw;
    float bh = __expf(ph) * ah;

    float bx = sx + wf;
    float by = sy + hf;
    float hbw = 0.5f * bw, hbh = 0.5f * bh;

    float mx = fminf(bx - hbw, g.gxm);
    float Mx = fmaxf(bx + hbw, g.gxM);
    float my = fminf(by - hbh, g.gym);
    float My = fmaxf(by + hbh, g.gyM);
    float cw = g.gw + bw - (Mx - mx);
    float ch = g.gh + bh - (My - my);
    float inter = (cw > 0.0f && ch > 0.0f) ? cw * ch : 0.0f;
    float uni = bw * bh + g.gwh - inter;

    // conf_mask^2: 0 if iou > 0.6 else 1.  iou>0.6 <=> inter>0.6*uni (uni>0).
    float cm2 = (inter > 0.6f * uni) ? 0.0f : 1.0f;

    float dx = sx - 0.5f;
    float dy = sy - 0.5f;
    return dx * dx + dy * dy + pw * pw + ph * ph + cm2 * (pc * pc);
}

// ---------------------------------------------------------------------------
// Single fused kernel. One block per (batch, anchor) plane, all cells generic.
// Blocks 0..511 additionally compute the per-batch special-cell correction
// (thread 0), overlapped with other blocks' streaming. The LAST block to
// finish reduces all partials + corrections and writes the output.
// Layout: pred[((b*125 + a*5 + comp) * 38 + h) * 38 + w]
// float4 path: 1444 = 4*361; plane stride 5776 B is 16B-aligned.
// ---------------------------------------------------------------------------
__global__ void __launch_bounds__(384)
k_main(const float* __restrict__ pred, const float* __restrict__ target,
       float* __restrict__ out) {
    int blk = blockIdx.x;
    int b = blk / NA;
    int a = blk - b * NA;

    GT g = make_gt(__ldg(&reinterpret_cast<const float4*>(target)[b]));
    float aw = c_anchors[a][0], ah = c_anchors[a][1];

    const float4* p = reinterpret_cast<const float4*>(pred + (size_t)blk * 5 * HWSZ);

    float acc = 0.0f;
    int q = threadIdx.x;
    if (q < 361) {
        float4 vx = p[q];
        float4 vy = p[q + 361];
        float4 vw = p[q + 722];
        float4 vh = p[q + 1083];
        float4 vc = p[q + 1444];

        float ax[4]  = {vx.x, vx.y, vx.z, vx.w};
        float ay[4]  = {vy.x, vy.y, vy.z, vy.w};
        float aww[4] = {vw.x, vw.y, vw.z, vw.w};
        float ahh[4] = {vh.x, vh.y, vh.z, vh.w};
        float ac[4]  = {vc.x, vc.y, vc.z, vc.w};

        int hw0 = q * 4;
#pragma unroll
        for (int j = 0; j < 4; j++) {
            int hw = hw0 + j;
            int h = hw / WDIM;
            int w = hw - h * WDIM;
            acc += cell_generic(ax[j], ay[j], aww[j], ahh[j], ac[j],
                                (float)w, (float)h, aw, ah, g);
        }
    }

    // block reduction: warp shuffle, then 12 warp sums
    for (int o = 16; o; o >>= 1) acc += __shfl_xor_sync(0xffffffffu, acc, o);
    __shared__ float warp_s[12];
    __shared__ int   s_last;
    int lane = threadIdx.x & 31;
    int wid = threadIdx.x >> 5;
    if (lane == 0) warp_s[wid] = acc;
    __syncthreads();

    if (threadIdx.x == 0) {
        float s = 0.0f;
#pragma unroll
        for (int i = 0; i < 12; i++) s += warp_s[i];
        g_partials[blk] = s;

        // ---- special-cell correction (first 512 blocks, batch = blk) ----
        if (blk < NB) {
            float4 t4 = __ldg(&reinterpret_cast<const float4*>(target)[blk]);
            float gx = t4.x * 38.0f;
            float gy = t4.y * 38.0f;
            float gw = t4.z * 38.0f;
            float gh = t4.w * 38.0f;

            // argmax over anchor IoU (origin-centered); '>' keeps first index.
            int best = 0;
            float best_iou = -1.0f;
#pragma unroll
            for (int k = 0; k < NA; k++) {
                float aw0 = c_anchors[k][0], ah0 = c_anchors[k][1];
                float inter0 = fminf(aw0, gw) * fminf(ah0, gh);
                float uni0 = aw0 * ah0 + gw * gh - inter0;
                float iou0 = inter0 / uni0;
                if (iou0 > best_iou) { best_iou = iou0; best = k; }
            }

            int gi = (int)gx;
            int gj = (int)gy;
            float baw = c_anchors[best][0], bah = c_anchors[best][1];

            long base = ((long)blk * 125 + (long)best * 5) * HWSZ
                      + (long)gj * WDIM + gi;
            float p0  = __ldg(pred + base);
            float p1  = __ldg(pred + base + HWSZ);
            float p2  = __ldg(pred + base + 2 * HWSZ);
            float p3  = __ldg(pred + base + 3 * HWSZ);
            float pcv = __ldg(pred + base + 4 * HWSZ);

            // generic contribution this cell received (identical math)
            GT gg = make_gt(t4);
            float gen = cell_generic(p0, p1, p2, p3, pcv,
                                     (float)gi, (float)gj, baw, bah, gg);

            // special contribution (targets via precise expf/logf)
            float sx = sigmoid_fast(p0);
            float sy = sigmoid_fast(p1);
            float pc = sigmoid_fast(pcv);

            float bx = 1.0f / (1.0f + expf(-p0)) + (float)gi;
            float by = 1.0f / (1.0f + expf(-p1)) + (float)gj;
            float bw = expf(p2) * baw;
            float bh = expf(p3) * bah;
            float mx = fminf(bx - bw * 0.5f, gx - gw * 0.5f);
            float Mx = fmaxf(bx + bw * 0.5f, gx + gw * 0.5f);
            float my = fminf(by - bh * 0.5f, gy - gh * 0.5f);
            float My = fmaxf(by + bh * 0.5f, gy + gh * 0.5f);
            float cw = bw + gw - (Mx - mx);
            float ch = bh + gh - (My - my);
            float inter = (cw > 0.0f && ch > 0.0f) ? cw * ch : 0.0f;
            float tconf = inter / (bw * bh + gw * gh - inter);

            float txs = gx - (float)gi;
            float tys = gy - (float)gj;
            float twt = logf(gw / baw);
            float tht = logf(gh / bah);

            float ddx = sx - txs;
            float ddy = sy - tys;
            float ddw = p2 - twt;
            float ddh = p3 - tht;
            float ddc = pc - tconf;
            float sp = ddx * ddx + ddy * ddy + ddw * ddw + ddh * ddh
                     + 5.0f * (ddc * ddc);

            g_corr[blk] = sp - gen;
        }

        __threadfence();
        unsigned int old = atomicAdd(&g_count, 1u);
        s_last = (old == NPLANES - 1) ? 1 : 0;
    }
    __syncthreads();

    // ---- last block: final deterministic reduction ----
    if (s_last) {
        int t = threadIdx.x;
        double s = 0.0;

        const float4* p4 = reinterpret_cast<const float4*>(g_partials); // 3200
        for (int i = t; i < NPLANES / 4; i += 384) {
            float4 v = __ldcg(&p4[i]);
            s += ((double)v.x + (double)v.y) + ((double)v.z + (double)v.w);
        }
        const float4* c4 = reinterpret_cast<const float4*>(g_corr);     // 128
        if (t < NB / 4) {
            float4 v = __ldcg(&c4[t]);
            s += ((double)v.x + (double)v.y) + ((double)v.z + (double)v.w);
        }

        for (int o = 16; o; o >>= 1) s += __shfl_xor_sync(0xffffffffu, s, o);
        __shared__ double ws[12];
        if (lane == 0) ws[wid] = s;
        __syncthreads();
        if (t == 0) {
            double tt = 0.0;
#pragma unroll
            for (int i = 0; i < 12; i++) tt += ws[i];
            out[0] = (float)(0.5 * tt);
            g_count = 0;   // reset for next (graph-replayed) launch
        }
    }
}

extern "C" void kernel_launch(void* const* d_in, const int* in_sizes, int n_in,
                              void* d_out, int out_size) {
    const float* pred = (const float*)d_in[0];
    const float* target = (const float*)d_in[1];
    float* out = (float*)d_out;

    k_main<<<NPLANES, 384>>>(pred, target, out);
}